// round 7
// baseline (speedup 1.0000x reference)
#include <cuda_runtime.h>
#include <cstdint>

// GraphSage 2-layer, tf32 tensor-core (mma.sync m16n8k8), templated on BM.
// out[b][o] = relu( sum_k comb[b][k]*W[o][k] ), comb = [self | mean of 10 neigh]
// Indices are staged to SMEM once (coalesced) so the gather loop has no
// dependent global index loads and low register pressure.

#define DD     128
#define KN     10
#define B1_SZ  40960
#define B2_SZ  4096

#define KT     64      // W k-tile
#define CPAD   260     // comb row stride (floats); 260%32==4 -> conflict-free frags
#define WPAD   68      // Wsh row stride (floats);  68%32==4  -> conflict-free frags

__device__ float g_h1[B1_SZ * DD];       // layer-1 hidden table (21 MB)

__device__ __forceinline__ uint32_t f2tf32(float f) {
    uint32_t u;
    asm("cvt.rna.tf32.f32 %0, %1;" : "=r"(u) : "f"(f));
    return u;
}

__device__ __forceinline__ float4 add4(float4 a, float4 b) {
    return make_float4(a.x + b.x, a.y + b.y, a.z + b.z, a.w + b.w);
}

__device__ __forceinline__ void mma_tf32(float& c0, float& c1, float& c2, float& c3,
                                         uint32_t a0, uint32_t a1, uint32_t a2, uint32_t a3,
                                         uint32_t b0, uint32_t b1) {
    asm volatile(
        "mma.sync.aligned.m16n8k8.row.col.f32.tf32.tf32.f32 "
        "{%0,%1,%2,%3}, {%4,%5,%6,%7}, {%8,%9}, {%0,%1,%2,%3};\n"
        : "+f"(c0), "+f"(c1), "+f"(c2), "+f"(c3)
        : "r"(a0), "r"(a1), "r"(a2), "r"(a3), "r"(b0), "r"(b1));
}

// Stage W[:, kt:kt+64] (fp32 in GMEM) as tf32 into Wsh[n][k]. CVTs hide under LDG.
__device__ __forceinline__ void stage_w(const float* __restrict__ W, float* Wsh,
                                        int kt, int tid) {
    #pragma unroll
    for (int it = 0; it < 8; it++) {
        const int e  = tid + it * 256;        // 0..2047
        const int n  = e >> 4;                // 0..127
        const int c4 = e & 15;                // float4 idx within k-tile
        float4 wv = __ldg(((const float4*)W) + n * 64 + (kt >> 2) + c4);
        uint4 wt = make_uint4(f2tf32(wv.x), f2tf32(wv.y), f2tf32(wv.z), f2tf32(wv.w));
        *((uint4*)(Wsh + n * WPAD + c4 * 4)) = wt;
    }
}

template <int BM_>
__global__ __launch_bounds__(256, 2)
void sage_tf32(const float* __restrict__ table,   // [T][128]
               const float* __restrict__ W,       // [128][256] fp32
               const int*   __restrict__ nodes,   // [B]
               const int*   __restrict__ neigh,   // [B][10]
               float*       __restrict__ out)     // [B][128]
{
    constexpr int R    = BM_ / 8;          // rows per warp (phase 1)
    constexpr int NM   = BM_ / 16;         // 16-row m-tiles
    constexpr int NCOL = 128 / (8 / NM);   // output cols per warp
    constexpr int NT   = NCOL / 8;         // n-subtiles per warp

    extern __shared__ __align__(16) float smem[];
    float* comb  = smem;                            // [BM_][CPAD]
    float* Wsh   = smem + BM_ * CPAD;               // [128][WPAD]
    int*   idxsh = (int*)(Wsh + DD * WPAD);         // [BM_] nodes + [BM_*KN] neigh

    const int tid  = threadIdx.x;
    const int warp = tid >> 5;
    const int lane = tid & 31;
    const int b0   = blockIdx.x * BM_;

    // ---- stage indices (coalesced, zero register cost in gather loop) ----
    if (tid < BM_) idxsh[tid] = __ldg(nodes + b0 + tid);
    #pragma unroll
    for (int e = tid; e < BM_ * KN; e += 256)
        idxsh[BM_ + e] = __ldg(neigh + b0 * KN + e);

    // ---- stage W k-tile 0 (independent of comb; overlaps above) ----
    stage_w(W, Wsh, 0, tid);
    __syncthreads();     // idxsh ready (Wsh tile 0 also ready for phase 2)

    // ================= Phase 1: gather + mean -> tf32 comb =================
    // Pair of rows per iteration: 22 LDS index reads (broadcast, cheap) then
    // 12 independent 512B gathers in flight; tree-reduce.
    #pragma unroll
    for (int i = 0; i < R; i += 2) {
        const int rA = warp * R + i, rB = rA + 1;

        const int nodeA = idxsh[rA];
        const int nodeB = idxsh[rB];
        float4 vA = __ldg(((const float4*)table) + (long long)nodeA * 32 + lane);
        float4 vB = __ldg(((const float4*)table) + (long long)nodeB * 32 + lane);

        float4 t[KN];
        #pragma unroll
        for (int k = 0; k < KN; k++) {
            const int idx = idxsh[BM_ + rA * KN + k];
            t[k] = __ldg(((const float4*)table) + (long long)idx * 32 + lane);
        }
        float4 sA = add4(add4(add4(t[0], t[1]), add4(t[2], t[3])),
                         add4(add4(t[4], t[5]), add4(t[6], t[7])));
        sA = add4(sA, add4(t[8], t[9]));

        float4 u[KN];
        #pragma unroll
        for (int k = 0; k < KN; k++) {
            const int idx = idxsh[BM_ + rB * KN + k];
            u[k] = __ldg(((const float4*)table) + (long long)idx * 32 + lane);
        }
        float4 sB = add4(add4(add4(u[0], u[1]), add4(u[2], u[3])),
                         add4(add4(u[4], u[5]), add4(u[6], u[7])));
        sB = add4(sB, add4(u[8], u[9]));

        const float s = 1.0f / (float)KN;
        uint4 svA = make_uint4(f2tf32(vA.x), f2tf32(vA.y), f2tf32(vA.z), f2tf32(vA.w));
        uint4 avA = make_uint4(f2tf32(sA.x * s), f2tf32(sA.y * s),
                               f2tf32(sA.z * s), f2tf32(sA.w * s));
        uint4 svB = make_uint4(f2tf32(vB.x), f2tf32(vB.y), f2tf32(vB.z), f2tf32(vB.w));
        uint4 avB = make_uint4(f2tf32(sB.x * s), f2tf32(sB.y * s),
                               f2tf32(sB.z * s), f2tf32(sB.w * s));
        ((uint4*)(comb + rA * CPAD))[lane]      = svA;
        ((uint4*)(comb + rA * CPAD + DD))[lane] = avA;
        ((uint4*)(comb + rB * CPAD))[lane]      = svB;
        ((uint4*)(comb + rB * CPAD + DD))[lane] = avB;
    }
    __syncthreads();

    // ================= Phase 2: tensor-core GEMM =================
    const int g     = lane >> 2;
    const int tig   = lane & 3;
    const int mbase = (warp % NM) * 16;
    const int nbase = (warp / NM) * NCOL;

    float acc[NT][4];
    #pragma unroll
    for (int nt = 0; nt < NT; nt++)
        #pragma unroll
        for (int j = 0; j < 4; j++) acc[nt][j] = 0.f;

    #pragma unroll
    for (int tix = 0; tix < (2 * DD) / KT; tix++) {
        const int kt = tix * KT;
        #pragma unroll
        for (int k0 = 0; k0 < KT; k0 += 8) {
            const uint32_t* ap = (const uint32_t*)(comb + (mbase + g) * CPAD + kt + k0 + tig);
            uint32_t a0 = ap[0];
            uint32_t a1 = ap[8 * CPAD];
            uint32_t a2 = ap[4];
            uint32_t a3 = ap[8 * CPAD + 4];
            #pragma unroll
            for (int nt = 0; nt < NT; nt++) {
                const uint32_t* bp = (const uint32_t*)(Wsh + (nbase + nt * 8 + g) * WPAD + k0 + tig);
                mma_tf32(acc[nt][0], acc[nt][1], acc[nt][2], acc[nt][3],
                         a0, a1, a2, a3, bp[0], bp[4]);
            }
        }
        if (tix < (2 * DD) / KT - 1) {
            __syncthreads();               // all warps done reading Wsh
            stage_w(W, Wsh, kt + KT, tid);
            __syncthreads();               // Wsh tile ready
        }
    }

    // ================= Epilogue: ReLU + store =================
    #pragma unroll
    for (int nt = 0; nt < NT; nt++) {
        const int row = b0 + mbase + g;
        const int col = nbase + nt * 8 + 2 * tig;
        float2 v0 = make_float2(fmaxf(acc[nt][0], 0.f), fmaxf(acc[nt][1], 0.f));
        float2 v1 = make_float2(fmaxf(acc[nt][2], 0.f), fmaxf(acc[nt][3], 0.f));
        *(float2*)(out + (long long)row * DD + col)       = v0;
        *(float2*)(out + (long long)(row + 8) * DD + col) = v1;
    }
}

extern "C" void kernel_launch(void* const* d_in, const int* in_sizes, int n_in,
                              void* d_out, int out_size)
{
    const float* raw    = (const float*)d_in[0];
    const float* W1     = (const float*)d_in[1];
    const float* W2     = (const float*)d_in[2];
    const int*   nodes1 = (const int*)  d_in[3];
    const int*   neigh1 = (const int*)  d_in[4];
    const int*   nodes2 = (const int*)  d_in[5];
    const int*   neigh2 = (const int*)  d_in[6];
    float*       out    = (float*)d_out;

    float* h1 = nullptr;
    cudaGetSymbolAddress((void**)&h1, g_h1);

    const int smem64 = (64 * CPAD + DD * WPAD + 64 * (KN + 1)) * (int)sizeof(float); // 104,192 B
    const int smem16 = (16 * CPAD + DD * WPAD + 16 * (KN + 1)) * (int)sizeof(float); //  52,160 B

    static bool attr_done = false;
    if (!attr_done) {
        cudaFuncSetAttribute(sage_tf32<64>,
                             cudaFuncAttributeMaxDynamicSharedMemorySize, smem64);
        cudaFuncSetAttribute(sage_tf32<16>,
                             cudaFuncAttributeMaxDynamicSharedMemorySize, smem16);
        attr_done = true;
    }

    sage_tf32<64><<<B1_SZ / 64, 256, smem64>>>(raw, W1, nodes1, neigh1, h1);
    sage_tf32<16><<<B2_SZ / 16, 256, smem16>>>(h1,  W2, nodes2, neigh2, out);
}

// round 10
// speedup vs baseline: 1.2815x; 1.2815x over previous
#include <cuda_runtime.h>
#include <cstdint>

// GraphSage 2-layer, tf32 tensor-core (mma.sync m16n8k8), templated on BM.
// out[b][o] = relu( sum_k comb[b][k]*W[o][k] ), comb = [self | mean of 10 neigh]
// Round-4 gather structure (register index prefetch per row-pair) +
// inline fp32->tf32 W staging (no separate conversion kernel).

#define DD     128
#define KN     10
#define B1_SZ  40960
#define B2_SZ  4096

#define KT     64      // W k-tile
#define CPAD   260     // comb row stride (floats); 260%32==4 -> conflict-free frags
#define WPAD   68      // Wsh row stride (floats);  68%32==4  -> conflict-free frags

__device__ float g_h1[B1_SZ * DD];       // layer-1 hidden table (21 MB)

__device__ __forceinline__ uint32_t f2tf32(float f) {
    uint32_t u;
    asm("cvt.rna.tf32.f32 %0, %1;" : "=r"(u) : "f"(f));
    return u;
}

__device__ __forceinline__ float4 add4(float4 a, float4 b) {
    return make_float4(a.x + b.x, a.y + b.y, a.z + b.z, a.w + b.w);
}

__device__ __forceinline__ void mma_tf32(float& c0, float& c1, float& c2, float& c3,
                                         uint32_t a0, uint32_t a1, uint32_t a2, uint32_t a3,
                                         uint32_t b0, uint32_t b1) {
    asm volatile(
        "mma.sync.aligned.m16n8k8.row.col.f32.tf32.tf32.f32 "
        "{%0,%1,%2,%3}, {%4,%5,%6,%7}, {%8,%9}, {%0,%1,%2,%3};\n"
        : "+f"(c0), "+f"(c1), "+f"(c2), "+f"(c3)
        : "r"(a0), "r"(a1), "r"(a2), "r"(a3), "r"(b0), "r"(b1));
}

// Stage W[:, kt:kt+64] (fp32 in GMEM) as tf32 into Wsh[n][k]. CVTs hide under LDG.
__device__ __forceinline__ void stage_w(const float* __restrict__ W, float* Wsh,
                                        int kt, int tid) {
    #pragma unroll
    for (int it = 0; it < 8; it++) {
        const int e  = tid + it * 256;        // 0..2047
        const int n  = e >> 4;                // 0..127
        const int c4 = e & 15;                // float4 idx within k-tile
        float4 wv = __ldg(((const float4*)W) + n * 64 + (kt >> 2) + c4);
        uint4 wt = make_uint4(f2tf32(wv.x), f2tf32(wv.y), f2tf32(wv.z), f2tf32(wv.w));
        *((uint4*)(Wsh + n * WPAD + c4 * 4)) = wt;
    }
}

template <int BM_>
__global__ __launch_bounds__(256, 2)
void sage_tf32(const float* __restrict__ table,   // [T][128]
               const float* __restrict__ W,       // [128][256] fp32
               const int*   __restrict__ nodes,   // [B]
               const int*   __restrict__ neigh,   // [B][10]
               float*       __restrict__ out)     // [B][128]
{
    constexpr int R    = BM_ / 8;          // rows per warp (phase 1)
    constexpr int NM   = BM_ / 16;         // 16-row m-tiles
    constexpr int NCOL = 128 / (8 / NM);   // output cols per warp
    constexpr int NT   = NCOL / 8;         // n-subtiles per warp

    extern __shared__ __align__(16) float smem[];
    float* comb = smem;                    // [BM_][CPAD]
    float* Wsh  = smem + BM_ * CPAD;       // [128][WPAD]

    const int tid  = threadIdx.x;
    const int warp = tid >> 5;
    const int lane = tid & 31;
    const int b0   = blockIdx.x * BM_;

    // stage W k-tile 0 (independent of comb; overlaps with gathers)
    stage_w(W, Wsh, 0, tid);

    // ================= Phase 1: gather + mean -> tf32 comb =================
    // Row pairs: prefetch this pair's 22 indices into registers, then issue
    // all 12 row gathers (MLP ~12); tree-reduce. No barrier before gathers.
    #pragma unroll
    for (int i = 0; i < R; i += 2) {
        const int rA = warp * R + i, rB = rA + 1;
        const int rowA = b0 + rA, rowB = b0 + rB;
        const int nodeA = __ldg(nodes + rowA);
        const int nodeB = __ldg(nodes + rowB);
        int idxA[KN], idxB[KN];
        #pragma unroll
        for (int k = 0; k < KN; k++) idxA[k] = __ldg(neigh + rowA * KN + k);
        #pragma unroll
        for (int k = 0; k < KN; k++) idxB[k] = __ldg(neigh + rowB * KN + k);

        float4 vA = __ldg(((const float4*)table) + (long long)nodeA * 32 + lane);
        float4 vB = __ldg(((const float4*)table) + (long long)nodeB * 32 + lane);

        float4 t[KN];
        #pragma unroll
        for (int k = 0; k < KN; k++)
            t[k] = __ldg(((const float4*)table) + (long long)idxA[k] * 32 + lane);
        float4 sA = add4(add4(add4(t[0], t[1]), add4(t[2], t[3])),
                         add4(add4(t[4], t[5]), add4(t[6], t[7])));
        sA = add4(sA, add4(t[8], t[9]));

        float4 u[KN];
        #pragma unroll
        for (int k = 0; k < KN; k++)
            u[k] = __ldg(((const float4*)table) + (long long)idxB[k] * 32 + lane);
        float4 sB = add4(add4(add4(u[0], u[1]), add4(u[2], u[3])),
                         add4(add4(u[4], u[5]), add4(u[6], u[7])));
        sB = add4(sB, add4(u[8], u[9]));

        const float s = 1.0f / (float)KN;
        uint4 svA = make_uint4(f2tf32(vA.x), f2tf32(vA.y), f2tf32(vA.z), f2tf32(vA.w));
        uint4 avA = make_uint4(f2tf32(sA.x * s), f2tf32(sA.y * s),
                               f2tf32(sA.z * s), f2tf32(sA.w * s));
        uint4 svB = make_uint4(f2tf32(vB.x), f2tf32(vB.y), f2tf32(vB.z), f2tf32(vB.w));
        uint4 avB = make_uint4(f2tf32(sB.x * s), f2tf32(sB.y * s),
                               f2tf32(sB.z * s), f2tf32(sB.w * s));
        ((uint4*)(comb + rA * CPAD))[lane]      = svA;
        ((uint4*)(comb + rA * CPAD + DD))[lane] = avA;
        ((uint4*)(comb + rB * CPAD))[lane]      = svB;
        ((uint4*)(comb + rB * CPAD + DD))[lane] = avB;
    }
    __syncthreads();

    // ================= Phase 2: tensor-core GEMM =================
    const int g     = lane >> 2;
    const int tig   = lane & 3;
    const int mbase = (warp % NM) * 16;
    const int nbase = (warp / NM) * NCOL;

    float acc[NT][4];
    #pragma unroll
    for (int nt = 0; nt < NT; nt++)
        #pragma unroll
        for (int j = 0; j < 4; j++) acc[nt][j] = 0.f;

    #pragma unroll
    for (int tix = 0; tix < (2 * DD) / KT; tix++) {
        const int kt = tix * KT;
        #pragma unroll
        for (int k0 = 0; k0 < KT; k0 += 8) {
            const uint32_t* ap = (const uint32_t*)(comb + (mbase + g) * CPAD + kt + k0 + tig);
            uint32_t a0 = ap[0];
            uint32_t a1 = ap[8 * CPAD];
            uint32_t a2 = ap[4];
            uint32_t a3 = ap[8 * CPAD + 4];
            #pragma unroll
            for (int nt = 0; nt < NT; nt++) {
                const uint32_t* bp = (const uint32_t*)(Wsh + (nbase + nt * 8 + g) * WPAD + k0 + tig);
                mma_tf32(acc[nt][0], acc[nt][1], acc[nt][2], acc[nt][3],
                         a0, a1, a2, a3, bp[0], bp[4]);
            }
        }
        if (tix < (2 * DD) / KT - 1) {
            __syncthreads();               // all warps done reading Wsh
            stage_w(W, Wsh, kt + KT, tid);
            __syncthreads();               // Wsh tile ready
        }
    }

    // ================= Epilogue: ReLU + store =================
    #pragma unroll
    for (int nt = 0; nt < NT; nt++) {
        const int row = b0 + mbase + g;
        const int col = nbase + nt * 8 + 2 * tig;
        float2 v0 = make_float2(fmaxf(acc[nt][0], 0.f), fmaxf(acc[nt][1], 0.f));
        float2 v1 = make_float2(fmaxf(acc[nt][2], 0.f), fmaxf(acc[nt][3], 0.f));
        *(float2*)(out + (long long)row * DD + col)       = v0;
        *(float2*)(out + (long long)(row + 8) * DD + col) = v1;
    }
}

extern "C" void kernel_launch(void* const* d_in, const int* in_sizes, int n_in,
                              void* d_out, int out_size)
{
    const float* raw    = (const float*)d_in[0];
    const float* W1     = (const float*)d_in[1];
    const float* W2     = (const float*)d_in[2];
    const int*   nodes1 = (const int*)  d_in[3];
    const int*   neigh1 = (const int*)  d_in[4];
    const int*   nodes2 = (const int*)  d_in[5];
    const int*   neigh2 = (const int*)  d_in[6];
    float*       out    = (float*)d_out;

    float* h1 = nullptr;
    cudaGetSymbolAddress((void**)&h1, g_h1);

    const int smem64 = (64 * CPAD + DD * WPAD) * (int)sizeof(float);  // 101,376 B
    const int smem16 = (16 * CPAD + DD * WPAD) * (int)sizeof(float);  //  51,456 B

    static bool attr_done = false;
    if (!attr_done) {
        cudaFuncSetAttribute(sage_tf32<64>,
                             cudaFuncAttributeMaxDynamicSharedMemorySize, smem64);
        cudaFuncSetAttribute(sage_tf32<16>,
                             cudaFuncAttributeMaxDynamicSharedMemorySize, smem16);
        attr_done = true;
    }

    sage_tf32<64><<<B1_SZ / 64, 256, smem64>>>(raw, W1, nodes1, neigh1, h1);
    sage_tf32<16><<<B2_SZ / 16, 256, smem16>>>(h1,  W2, nodes2, neigh2, out);
}